// round 2
// baseline (speedup 1.0000x reference)
#include <cuda_runtime.h>

// Problem constants
constexpr int NB   = 32;      // batch
constexpr int C    = 256;     // channels
constexpr int HW   = 4096;    // 64*64
constexpr int G    = 8;       // groups
constexpr int GS   = 32;      // channels per group
constexpr int NTOT = NB * HW; // samples per channel = 131072
constexpr float EPSV = 1e-5f;

// Scratch (device globals — no allocations allowed)
__device__ float g_S1[G][GS];          // per-channel sums
__device__ float g_S2[G][GS][GS];      // per-group sum of products
__device__ float g_wmw[G][GS][GS];     // whitening matrix, weight-folded
__device__ float g_beta[G][GS];        // bias - wmw @ mean  (affine fold)

// ---------------------------------------------------------------------------
// Kernel 0: zero the accumulators (must be re-zeroed every launch)
// ---------------------------------------------------------------------------
__global__ void k_zero() {
    int t = threadIdx.x;
    if (t < G * GS) ((float*)g_S1)[t] = 0.f;
    for (int i = t; i < G * GS * GS; i += 256) ((float*)g_S2)[i] = 0.f;
}

// ---------------------------------------------------------------------------
// Kernel 1: covariance accumulation.
// Grid: 512 blocks = G(8) x B(32) x 2 hw-halves. Each block: 32ch x 2048 cols.
// smem tile layout [k][c] with stride 33: b-operand conflict-free, a-operands
// warp-broadcast. Each thread owns a 4x1 strip of the 32x32 output.
// Warp 0 also accumulates per-channel sums (its b-operand IS x[c][k]).
// ---------------------------------------------------------------------------
__global__ void __launch_bounds__(256) k_cov(const float* __restrict__ x) {
    __shared__ float sm[128 * 33];
    const int bx = blockIdx.x;
    const int g = bx >> 6;
    const int b = (bx >> 1) & 31;
    const int s = bx & 1;
    const float* xb = x + (size_t)(b * C + g * GS) * HW + s * 2048;

    const int tid = threadIdx.x;
    const int r0 = (tid >> 5) << 2;   // row base (warp-uniform)
    const int cc = tid & 31;          // column (lane)

    float a0 = 0.f, a1 = 0.f, a2 = 0.f, a3 = 0.f, s1 = 0.f;

    for (int t16 = 0; t16 < 16; t16++) {
        const float* xt = xb + t16 * 128;
        // Load 32x128 tile: consecutive threads -> consecutive k (coalesced),
        // STS banks (k + c) % 32 -> conflict-free.
        for (int i = tid; i < 32 * 128; i += 256) {
            int c = i >> 7, k = i & 127;
            sm[k * 33 + c] = xt[c * HW + k];
        }
        __syncthreads();

        #pragma unroll 8
        for (int k = 0; k < 128; k++) {
            const float* row = &sm[k * 33];
            float bv = row[cc];
            a0 += row[r0 + 0] * bv;
            a1 += row[r0 + 1] * bv;
            a2 += row[r0 + 2] * bv;
            a3 += row[r0 + 3] * bv;
            if (r0 == 0) s1 += bv;    // warp 0 only (warp-uniform branch)
        }
        __syncthreads();
    }

    atomicAdd(&g_S2[g][r0 + 0][cc], a0);
    atomicAdd(&g_S2[g][r0 + 1][cc], a1);
    atomicAdd(&g_S2[g][r0 + 2][cc], a2);
    atomicAdd(&g_S2[g][r0 + 3][cc], a3);
    if (r0 == 0) atomicAdd(&g_S1[g][cc], s1);
}

// ---------------------------------------------------------------------------
// Kernel 2: build sigma, compute sigma^{-1/2} via coupled Newton-Schulz,
// fold in weight / mean / bias. One block (32x32 threads) per group.
//   sigma = S2 - S1 S1^T / N + eps I
//   A = sigma / ||sigma||_F  (eigenvalues in (0,1], here ~0.177 +- 5%)
//   Y0=A, Z0=I;  T=3I-ZY; Y=0.5 Y T; Z=0.5 T Z  -> Z -> A^{-1/2}
//   wm = Z / sqrt(||sigma||_F)
// ---------------------------------------------------------------------------
__global__ void __launch_bounds__(1024) k_ns(const float* __restrict__ w,
                                             const float* __restrict__ bias) {
    const int g = blockIdx.x;
    const int tid = threadIdx.x;
    const int i = tid >> 5, j = tid & 31;

    __shared__ float Y[32 * 33], Z[32 * 33], T[32 * 33];
    __shared__ float red[32];

    const float s1i = g_S1[g][i];
    const float s1j = g_S1[g][j];
    float sig = g_S2[g][i][j] - s1i * s1j * (1.0f / NTOT) + (i == j ? EPSV : 0.f);

    // Frobenius norm^2 (block reduce)
    float v = sig * sig;
    #pragma unroll
    for (int o = 16; o; o >>= 1) v += __shfl_xor_sync(0xFFFFFFFFu, v, o);
    if (j == 0) red[i] = v;
    __syncthreads();
    if (tid < 32) {
        float r = red[tid];
        #pragma unroll
        for (int o = 16; o; o >>= 1) r += __shfl_xor_sync(0xFFFFFFFFu, r, o);
        if (tid == 0) red[0] = r;
    }
    __syncthreads();
    const float fro = sqrtf(red[0]);

    Y[i * 33 + j] = sig / fro;
    Z[i * 33 + j] = (i == j) ? 1.f : 0.f;
    __syncthreads();

    for (int it = 0; it < 10; it++) {
        float t = (i == j) ? 3.f : 0.f;
        #pragma unroll
        for (int k = 0; k < 32; k++) t -= Z[i * 33 + k] * Y[k * 33 + j];
        T[i * 33 + j] = t;             // T not read by anyone yet
        __syncthreads();
        float yn = 0.f, zn = 0.f;
        #pragma unroll
        for (int k = 0; k < 32; k++) {
            yn += Y[i * 33 + k] * T[k * 33 + j];
            zn += T[i * 33 + k] * Z[k * 33 + j];
        }
        __syncthreads();               // everyone done reading old Y, Z
        Y[i * 33 + j] = 0.5f * yn;
        Z[i * 33 + j] = 0.5f * zn;
        __syncthreads();
    }

    const float wmw = Z[i * 33 + j] * rsqrtf(fro) * w[g * GS + i];
    g_wmw[g][i][j] = wmw;

    // beta_i = bias_i - sum_j wmw[i][j] * mean_j
    float bv = wmw * (s1j * (1.0f / NTOT));
    #pragma unroll
    for (int o = 16; o; o >>= 1) bv += __shfl_xor_sync(0xFFFFFFFFu, bv, o);
    if (j == 0) g_beta[g][i] = bias[g * GS + i] - bv;
}

// ---------------------------------------------------------------------------
// Kernel 3: apply. out[b, g*32+i, hw] = sum_e wmw[g][i][e]*x[b,g*32+e,hw] + beta[g][i]
// Each thread owns one (b, g, hw) column: 32 coalesced LDG into registers,
// WM rows via broadcast LDS.128, 32 coalesced STG.
// ---------------------------------------------------------------------------
__global__ void __launch_bounds__(256) k_apply(const float* __restrict__ x,
                                               float* __restrict__ out) {
    __shared__ float swm[GS * GS];
    __shared__ float sb[GS];

    const int q0 = blockIdx.x * 256;
    const int gb = q0 >> 17;                 // group (constant per block)
    for (int i = threadIdx.x; i < GS * GS; i += 256)
        swm[i] = ((const float*)g_wmw)[gb * GS * GS + i];
    if (threadIdx.x < GS) sb[threadIdx.x] = g_beta[gb][threadIdx.x];
    __syncthreads();

    const int q  = q0 + threadIdx.x;
    const int hw = q & (HW - 1);
    const int b  = (q >> 12) & 31;

    const size_t base = (size_t)(b * C + gb * GS) * HW + hw;
    const float* xp = x + base;
    float* op = out + base;

    float xv[GS];
    #pragma unroll
    for (int e = 0; e < GS; e++) xv[e] = xp[(size_t)e * HW];

    #pragma unroll 4
    for (int i2 = 0; i2 < GS; i2++) {
        const float4* wr = (const float4*)&swm[i2 * GS];
        float acc0 = 0.f, acc1 = 0.f, acc2 = 0.f, acc3 = 0.f;
        #pragma unroll
        for (int e4 = 0; e4 < 8; e4++) {
            float4 wv = wr[e4];
            acc0 += wv.x * xv[4 * e4 + 0];
            acc1 += wv.y * xv[4 * e4 + 1];
            acc2 += wv.z * xv[4 * e4 + 2];
            acc3 += wv.w * xv[4 * e4 + 3];
        }
        op[(size_t)i2 * HW] = (acc0 + acc1) + (acc2 + acc3) + sb[i2];
    }
}

// ---------------------------------------------------------------------------
extern "C" void kernel_launch(void* const* d_in, const int* in_sizes, int n_in,
                              void* d_out, int out_size) {
    const float* x    = (const float*)d_in[0];
    const float* w    = (const float*)d_in[1];
    const float* bias = (const float*)d_in[2];
    float* out        = (float*)d_out;

    k_zero<<<1, 256>>>();
    k_cov<<<512, 256>>>(x);
    k_ns<<<G, 1024>>>(w, bias);
    k_apply<<<(G * NB * HW) / 256, 256>>>(x, out);
}

// round 3
// speedup vs baseline: 1.5582x; 1.5582x over previous
#include <cuda_runtime.h>

using u64 = unsigned long long;

// Problem constants
constexpr int NB   = 32;      // batch
constexpr int C    = 256;     // channels
constexpr int HW   = 4096;    // 64*64
constexpr int G    = 8;       // groups
constexpr int GS   = 32;      // channels per group
constexpr int NTOT = NB * HW; // samples per channel = 131072
constexpr float EPSV = 1e-5f;

constexpr int NBLK = 1024;    // cov blocks (G * NB * 4 k-slices)
constexpr int PPG  = 128;     // partials per group

// Scratch (device globals — no allocations allowed)
__device__ float g_p1[NBLK][GS];          // per-block partial channel sums
__device__ float g_p2[NBLK][GS][GS];      // per-block partial products
__device__ float g_wmw[G][GS][GS];        // whitening matrix, weight-folded
__device__ float g_beta[G][GS];           // bias - wmw @ mean

// ---- packed f32x2 helpers (sm_103a FFMA2) ----------------------------------
__device__ __forceinline__ u64 f2pk(float lo, float hi) {
    u64 r; asm("mov.b64 %0, {%1, %2};" : "=l"(r) : "f"(lo), "f"(hi)); return r;
}
__device__ __forceinline__ void f2un(u64 v, float& lo, float& hi) {
    asm("mov.b64 {%0, %1}, %2;" : "=f"(lo), "=f"(hi) : "l"(v));
}
__device__ __forceinline__ u64 ffma2(u64 a, u64 b, u64 c) {
    u64 d; asm("fma.rn.f32x2 %0, %1, %2, %3;" : "=l"(d) : "l"(a), "l"(b), "l"(c));
    return d;
}
__device__ __forceinline__ u64 fadd2(u64 a, u64 b) {
    u64 d; asm("add.rn.f32x2 %0, %1, %2;" : "=l"(d) : "l"(a), "l"(b)); return d;
}

// ---------------------------------------------------------------------------
// Kernel 1: covariance partials. 1024 blocks = (g, b, k-slice/4) x 128 threads.
// Each block: 32 channels x 1024 k. smem tile [c][k] stride 132 (16B aligned,
// odd in float4 units -> conflict-free LDS.128 for rows and columns).
// Reduction dim (k) is f32x2-packed: both operands natural, hadd at the end.
// Thread = 4 rows x 2 cols of the 32x32 output.
// ---------------------------------------------------------------------------
__global__ void __launch_bounds__(128) k_cov(const float* __restrict__ x) {
    __shared__ __align__(16) float sm[GS * 132];
    const int bx = blockIdx.x;
    const int g = bx >> 7;
    const int b = (bx >> 2) & 31;
    const int s = bx & 3;
    const float* xb = x + (size_t)(b * C + g * GS) * HW + s * 1024;

    const int tid = threadIdx.x;
    const int cp  = tid & 15;          // column pair id
    const int rg  = tid >> 4;          // row group 0..7
    const int c0 = cp, c1 = cp + 16;

    u64 acc[4][2];
    #pragma unroll
    for (int u = 0; u < 4; u++) { acc[u][0] = 0ull; acc[u][1] = 0ull; }
    u64 s1a = 0ull, s1b = 0ull;

    for (int t8 = 0; t8 < 8; t8++) {
        const float* xt = xb + t8 * 128;
        // Load 32ch x 128k tile, float4, fully coalesced; one warp per channel row.
        #pragma unroll
        for (int j = 0; j < 8; j++) {
            int idx = tid + 128 * j;           // float4 index
            int c = idx >> 5, k4 = idx & 31;
            *(float4*)&sm[c * 132 + 4 * k4] =
                *(const float4*)&xt[(size_t)c * HW + 4 * k4];
        }
        __syncthreads();

        const bool doS1 = (rg == t8);          // each row-group sums one tile
        #pragma unroll 8
        for (int k4 = 0; k4 < 32; k4++) {
            ulonglong2 b0 = *(const ulonglong2*)&sm[c0 * 132 + 4 * k4];
            ulonglong2 b1 = *(const ulonglong2*)&sm[c1 * 132 + 4 * k4];
            #pragma unroll
            for (int u = 0; u < 4; u++) {
                ulonglong2 a = *(const ulonglong2*)&sm[(rg * 4 + u) * 132 + 4 * k4];
                acc[u][0] = ffma2(a.x, b0.x, acc[u][0]);
                acc[u][0] = ffma2(a.y, b0.y, acc[u][0]);
                acc[u][1] = ffma2(a.x, b1.x, acc[u][1]);
                acc[u][1] = ffma2(a.y, b1.y, acc[u][1]);
            }
            if (doS1) {
                s1a = fadd2(s1a, b0.x); s1a = fadd2(s1a, b0.y);
                s1b = fadd2(s1b, b1.x); s1b = fadd2(s1b, b1.y);
            }
        }
        __syncthreads();
    }

    // Emit product partials
    #pragma unroll
    for (int u = 0; u < 4; u++) {
        float lo, hi;
        f2un(acc[u][0], lo, hi); g_p2[bx][rg * 4 + u][c0] = lo + hi;
        f2un(acc[u][1], lo, hi); g_p2[bx][rg * 4 + u][c1] = lo + hi;
    }
    // Emit channel-sum partials (reduce the 8 row-group pieces via smem)
    {
        float lo, hi;
        f2un(s1a, lo, hi); sm[rg * GS + c0] = lo + hi;
        f2un(s1b, lo, hi); sm[rg * GS + c1] = lo + hi;
    }
    __syncthreads();
    if (tid < GS) {
        float v = 0.f;
        #pragma unroll
        for (int r = 0; r < 8; r++) v += sm[r * GS + tid];
        g_p1[bx][tid] = v;
    }
}

// ---------------------------------------------------------------------------
// Kernel 2: reduce partials -> sigma; sigma^{-1/2} via coupled Newton-Schulz
// with Gershgorin scaling (lambda/s in ~[0.85,1] here -> 7 iters << 1e-9);
// fold weight / mean / bias. One 1024-thread block per group.
// ---------------------------------------------------------------------------
__global__ void __launch_bounds__(1024) k_ns(const float* __restrict__ w,
                                             const float* __restrict__ bias) {
    const int g = blockIdx.x;
    const int tid = threadIdx.x;
    const int i = tid >> 5, j = tid & 31;

    __shared__ float Y[32 * 33], Z[32 * 33], T[32 * 33];
    __shared__ float red[32], sS1[32];

    // Reduce product partials
    float s2 = 0.f;
    const int pb = g * PPG;
    #pragma unroll 4
    for (int p = 0; p < PPG; p++) s2 += g_p2[pb + p][i][j];
    // Reduce channel-sum partials
    if (tid < 32) {
        float v = 0.f;
        #pragma unroll 4
        for (int p = 0; p < PPG; p++) v += g_p1[pb + p][tid];
        sS1[tid] = v;
    }
    __syncthreads();
    const float m_i = sS1[i], m_j = sS1[j];
    float sig = s2 - m_i * m_j * (1.0f / NTOT) + (i == j ? EPSV : 0.f);

    // Gershgorin bound: s = max_i sum_j |sig_ij| >= lambda_max
    float av = fabsf(sig);
    #pragma unroll
    for (int o = 16; o; o >>= 1) av += __shfl_xor_sync(0xFFFFFFFFu, av, o);
    if (j == 0) red[i] = av;
    __syncthreads();
    if (tid < 32) {
        float m = red[tid];
        #pragma unroll
        for (int o = 16; o; o >>= 1) m = fmaxf(m, __shfl_xor_sync(0xFFFFFFFFu, m, o));
        if (tid == 0) red[0] = m;
    }
    __syncthreads();
    const float s = red[0];

    Y[i * 33 + j] = sig / s;
    Z[i * 33 + j] = (i == j) ? 1.f : 0.f;
    __syncthreads();

    for (int it = 0; it < 7; it++) {
        float t = (i == j) ? 3.f : 0.f;
        #pragma unroll
        for (int k = 0; k < 32; k++) t -= Z[i * 33 + k] * Y[k * 33 + j];
        T[i * 33 + j] = t;
        __syncthreads();
        float yn = 0.f, zn = 0.f;
        #pragma unroll
        for (int k = 0; k < 32; k++) {
            yn += Y[i * 33 + k] * T[k * 33 + j];
            zn += T[i * 33 + k] * Z[k * 33 + j];
        }
        __syncthreads();
        Y[i * 33 + j] = 0.5f * yn;
        Z[i * 33 + j] = 0.5f * zn;
        __syncthreads();
    }

    const float wmv = Z[i * 33 + j] * rsqrtf(s) * w[g * GS + i];
    g_wmw[g][i][j] = wmv;

    float bv = wmv * (m_j * (1.0f / NTOT));
    #pragma unroll
    for (int o = 16; o; o >>= 1) bv += __shfl_xor_sync(0xFFFFFFFFu, bv, o);
    if (j == 0) g_beta[g][i] = bias[g * GS + i] - bv;
}

// ---------------------------------------------------------------------------
// Kernel 3: apply, f32x2-packed over the channel (e) reduction.
// Thread = one hw pair (2 columns). x loaded as float2 per channel, repacked
// into e-pairs; wm rows read as broadcast ulonglong2 (natural packing, no dup).
// ---------------------------------------------------------------------------
__global__ void __launch_bounds__(256) k_apply(const float* __restrict__ x,
                                               float* __restrict__ out) {
    __shared__ __align__(16) float swm[GS * GS];
    __shared__ float sb[GS];

    const int gb = blockIdx.x >> 8;              // 256 blocks per group
    for (int t = threadIdx.x; t < GS * GS; t += 256)
        swm[t] = ((const float*)g_wmw)[gb * GS * GS + t];
    if (threadIdx.x < GS) sb[threadIdx.x] = g_beta[gb][threadIdx.x];
    __syncthreads();

    const int p  = ((blockIdx.x & 255) << 8) + threadIdx.x;  // pair idx in group
    const int hw = (p & 2047) * 2;
    const int b  = p >> 11;
    const size_t base = (size_t)(b * C + gb * GS) * HW + hw;
    const float* xp = x + base;
    float* op = out + base;

    // Load 32 channels x 2 columns, repack to e-pairs per column
    u64 xv0[16], xv1[16];
    #pragma unroll
    for (int e2 = 0; e2 < 16; e2++) {
        float2 lo = *(const float2*)&xp[(size_t)(2 * e2) * HW];
        float2 hi = *(const float2*)&xp[(size_t)(2 * e2 + 1) * HW];
        xv0[e2] = f2pk(lo.x, hi.x);
        xv1[e2] = f2pk(lo.y, hi.y);
    }

    #pragma unroll 4
    for (int i = 0; i < GS; i++) {
        u64 bpk = f2pk(sb[i], 0.f);
        u64 a0 = bpk, a1 = bpk;
        #pragma unroll
        for (int e2 = 0; e2 < 16; e2 += 2) {
            ulonglong2 wv = *(const ulonglong2*)&swm[i * GS + 2 * e2];
            a0 = ffma2(xv0[e2],     wv.x, a0);
            a0 = ffma2(xv0[e2 + 1], wv.y, a0);
            a1 = ffma2(xv1[e2],     wv.x, a1);
            a1 = ffma2(xv1[e2 + 1], wv.y, a1);
        }
        float l0, h0, l1, h1;
        f2un(a0, l0, h0); f2un(a1, l1, h1);
        float2 r; r.x = l0 + h0; r.y = l1 + h1;
        *(float2*)&op[(size_t)i * HW] = r;
    }
}

// ---------------------------------------------------------------------------
extern "C" void kernel_launch(void* const* d_in, const int* in_sizes, int n_in,
                              void* d_out, int out_size) {
    const float* x    = (const float*)d_in[0];
    const float* w    = (const float*)d_in[1];
    const float* bias = (const float*)d_in[2];
    float* out        = (float*)d_out;

    k_cov<<<NBLK, 128>>>(x);
    k_ns<<<G, 1024>>>(w, bias);
    k_apply<<<(G * NB * HW / 2) / 256, 256>>>(x, out);
}

// round 6
// speedup vs baseline: 1.9150x; 1.2290x over previous
#include <cuda_runtime.h>
#include <cstdint>

using u64 = unsigned long long;

// Problem constants
constexpr int NB   = 32;
constexpr int C    = 256;
constexpr int HW   = 4096;
constexpr int G    = 8;
constexpr int GS   = 32;
constexpr int NTOT = NB * HW;          // 131072
constexpr float EPSV = 1e-5f;

constexpr int PPG = 32;                // partials per group (one per batch)

// Scratch (device globals — no allocations allowed)
__device__ float g_p2[G * PPG][GS][GS];   // per-block cov partials
__device__ float g_p1[G * PPG][GS];       // per-block sum partials
__device__ u64   g_wm2[G][GS][GS];        // (w,w) duplicated whitening entries
__device__ u64   g_beta2[G][GS];          // (beta,beta)

// ---- packed f32x2 helpers ---------------------------------------------------
__device__ __forceinline__ u64 f2pk(float lo, float hi) {
    u64 r; asm("mov.b64 %0, {%1, %2};" : "=l"(r) : "f"(lo), "f"(hi)); return r;
}
__device__ __forceinline__ u64 ffma2(u64 a, u64 b, u64 c) {
    u64 d; asm("fma.rn.f32x2 %0, %1, %2, %3;" : "=l"(d) : "l"(a), "l"(b), "l"(c));
    return d;
}
__device__ __forceinline__ u64 fadd2(u64 a, u64 b) {
    u64 d; asm("add.rn.f32x2 %0, %1, %2;" : "=l"(d) : "l"(a), "l"(b)); return d;
}

// ---- misc PTX ---------------------------------------------------------------
__device__ __forceinline__ uint32_t smem_u32(const void* p) {
    uint32_t a;
    asm("{ .reg .u64 t; cvta.to.shared.u64 t, %1; cvt.u32.u64 %0, t; }"
        : "=r"(a) : "l"(p));
    return a;
}
__device__ __forceinline__ void cp16(uint32_t dst, const void* src) {
    asm volatile("cp.async.cg.shared.global [%0], [%1], 16;"
                 :: "r"(dst), "l"(src) : "memory");
}
__device__ __forceinline__ uint32_t cvt_tf32(float f) {
    uint32_t r; asm("cvt.rna.tf32.f32 %0, %1;" : "=r"(r) : "f"(f)); return r;
}
__device__ __forceinline__ void mma_tf32(float& c0, float& c1, float& c2, float& c3,
                                         uint32_t a0, uint32_t a1, uint32_t a2,
                                         uint32_t a3, uint32_t b0, uint32_t b1) {
    asm volatile(
        "mma.sync.aligned.m16n8k8.row.col.f32.tf32.tf32.f32 "
        "{%0,%1,%2,%3}, {%4,%5,%6,%7}, {%8,%9}, {%0,%1,%2,%3};"
        : "+f"(c0), "+f"(c1), "+f"(c2), "+f"(c3)
        : "r"(a0), "r"(a1), "r"(a2), "r"(a3), "r"(b0), "r"(b1));
}

constexpr int RSTRIDE = 132;           // smem row stride in floats (132%32==4)
constexpr int TILEK   = 128;           // k per tile
constexpr uint32_t ONE_TF = 0x3F800000u;

// ---------------------------------------------------------------------------
// Kernel 1: covariance via mma.sync tf32. 256 blocks = (g, b), 8 warps each.
// Block computes partial Sigma_g over K=4096 (one batch image).
// smem tile [32ch][128k] stride 132; A fragments double as B fragments
// (Sigma = X X^T), so inner k8 step is 8 LDS + 8 cvt + 10 MMA.
// Two extra ones-MMAs accumulate per-channel sums.
// ---------------------------------------------------------------------------
__global__ void __launch_bounds__(256) k_cov(const float* __restrict__ x) {
    __shared__ __align__(16) float sbuf[2][32 * RSTRIDE];   // 33792 B, reused for reduce
    __shared__ float ssum[8][32];

    const int tid = threadIdx.x;
    const int wid = tid >> 5, lane = tid & 31;
    const int g1 = lane >> 2, t4 = lane & 3;   // mma fragment coords

    const int bx = blockIdx.x;
    const int g = bx >> 5, b = bx & 31;
    const float* xb = x + (size_t)(b * C + g * GS) * HW;

    const uint32_t sb0 = smem_u32(&sbuf[0][0]);
    const uint32_t sb1 = smem_u32(&sbuf[1][0]);

    // fill tile t into buffer: warp w writes row (j*8 + w), lanes -> 16B chunks
    auto fill = [&](int t, uint32_t dstb) {
        const float* xt = xb + t * TILEK;
        #pragma unroll
        for (int j = 0; j < 4; j++) {
            int c = j * 256 + tid;
            int row = c >> 5, kq = c & 31;
            cp16(dstb + row * (RSTRIDE * 4) + kq * 16,
                 xt + (size_t)row * HW + kq * 4);
        }
        asm volatile("cp.async.commit_group;" ::: "memory");
    };

    float acc[2][4][4];                 // [mtile][ntile][frag]
    float oacc[2][4];                   // ones accumulators [mtile][frag]
    #pragma unroll
    for (int m = 0; m < 2; m++) {
        #pragma unroll
        for (int n = 0; n < 4; n++)
            acc[m][n][0] = acc[m][n][1] = acc[m][n][2] = acc[m][n][3] = 0.f;
        oacc[m][0] = oacc[m][1] = oacc[m][2] = oacc[m][3] = 0.f;
    }

    fill(0, sb0);
    for (int t = 0; t < 32; t++) {
        const uint32_t cur = (t & 1) ? sb1 : sb0;
        if (t + 1 < 32) {
            fill(t + 1, (t & 1) ? sb0 : sb1);
            asm volatile("cp.async.wait_group 1;" ::: "memory");
        } else {
            asm volatile("cp.async.wait_group 0;" ::: "memory");
        }
        __syncthreads();

        const float* sm = (t & 1) ? &sbuf[1][0] : &sbuf[0][0];
        #pragma unroll
        for (int kk = 0; kk < 2; kk++) {
            const int kb = wid * 16 + kk * 8;
            uint32_t af[2][4];
            #pragma unroll
            for (int m = 0; m < 2; m++) {
                const float* r0 = sm + (m * 16 + g1) * RSTRIDE + kb + t4;
                const float* r1 = sm + (m * 16 + g1 + 8) * RSTRIDE + kb + t4;
                af[m][0] = cvt_tf32(r0[0]);
                af[m][1] = cvt_tf32(r1[0]);
                af[m][2] = cvt_tf32(r0[4]);
                af[m][3] = cvt_tf32(r1[4]);
            }
            // B fragments alias A fragments (Sigma = X X^T):
            // ntile0:{af00,af02} ntile1:{af01,af03} ntile2:{af10,af12} ntile3:{af11,af13}
            #pragma unroll
            for (int m = 0; m < 2; m++) {
                mma_tf32(acc[m][0][0], acc[m][0][1], acc[m][0][2], acc[m][0][3],
                         af[m][0], af[m][1], af[m][2], af[m][3], af[0][0], af[0][2]);
                mma_tf32(acc[m][1][0], acc[m][1][1], acc[m][1][2], acc[m][1][3],
                         af[m][0], af[m][1], af[m][2], af[m][3], af[0][1], af[0][3]);
                mma_tf32(acc[m][2][0], acc[m][2][1], acc[m][2][2], acc[m][2][3],
                         af[m][0], af[m][1], af[m][2], af[m][3], af[1][0], af[1][2]);
                mma_tf32(acc[m][3][0], acc[m][3][1], acc[m][3][2], acc[m][3][3],
                         af[m][0], af[m][1], af[m][2], af[m][3], af[1][1], af[1][3]);
                mma_tf32(oacc[m][0], oacc[m][1], oacc[m][2], oacc[m][3],
                         af[m][0], af[m][1], af[m][2], af[m][3], ONE_TF, ONE_TF);
            }
        }
        __syncthreads();
    }

    // Cross-warp reduction: overlay sred[8][32][33] on sbuf.
    float* sred = &sbuf[0][0];          // 8 * 1056 floats == 2 * 4224 floats
    #pragma unroll
    for (int m = 0; m < 2; m++) {
        const int r0 = m * 16 + g1, r1 = r0 + 8;
        #pragma unroll
        for (int n = 0; n < 4; n++) {
            const int cb = n * 8 + 2 * t4;
            sred[wid * 1056 + r0 * 33 + cb]     = acc[m][n][0];
            sred[wid * 1056 + r0 * 33 + cb + 1] = acc[m][n][1];
            sred[wid * 1056 + r1 * 33 + cb]     = acc[m][n][2];
            sred[wid * 1056 + r1 * 33 + cb + 1] = acc[m][n][3];
        }
        if (t4 == 0) {                  // column 0 of ones-MMA = row sums
            ssum[wid][r0] = oacc[m][0];
            ssum[wid][r1] = oacc[m][2];
        }
    }
    __syncthreads();

    #pragma unroll
    for (int q = 0; q < 4; q++) {
        const int idx = tid * 4 + q;    // 0..1023
        const int r = idx >> 5, c = idx & 31;
        float v = 0.f;
        #pragma unroll
        for (int w = 0; w < 8; w++) v += sred[w * 1056 + r * 33 + c];
        g_p2[bx][r][c] = v;
    }
    if (tid < 32) {
        float v = 0.f;
        #pragma unroll
        for (int w = 0; w < 8; w++) v += ssum[w][tid];
        g_p1[bx][tid] = v;
    }
}

// ---------------------------------------------------------------------------
// Kernel 2: reduce partials -> sigma; sigma^{-1/2} via Newton-Schulz with
// Gershgorin scaling; emit duplicated-pair tables for the f32x2 apply.
// ---------------------------------------------------------------------------
__global__ void __launch_bounds__(1024) k_ns(const float* __restrict__ w,
                                             const float* __restrict__ bias) {
    const int g = blockIdx.x;
    const int tid = threadIdx.x;
    const int i = tid >> 5, j = tid & 31;

    __shared__ float Y[32 * 33], Z[32 * 33], T[32 * 33];
    __shared__ float red[32], sS1[32];

    float s2 = 0.f;
    #pragma unroll 4
    for (int p = 0; p < PPG; p++) s2 += g_p2[g * PPG + p][i][j];
    if (tid < 32) {
        float v = 0.f;
        #pragma unroll 4
        for (int p = 0; p < PPG; p++) v += g_p1[g * PPG + p][tid];
        sS1[tid] = v;
    }
    __syncthreads();
    const float m_i = sS1[i], m_j = sS1[j];
    float sig = s2 - m_i * m_j * (1.0f / NTOT) + (i == j ? EPSV : 0.f);

    // Gershgorin bound >= lambda_max
    float av = fabsf(sig);
    #pragma unroll
    for (int o = 16; o; o >>= 1) av += __shfl_xor_sync(0xFFFFFFFFu, av, o);
    if (j == 0) red[i] = av;
    __syncthreads();
    if (tid < 32) {
        float m = red[tid];
        #pragma unroll
        for (int o = 16; o; o >>= 1) m = fmaxf(m, __shfl_xor_sync(0xFFFFFFFFu, m, o));
        if (tid == 0) red[0] = m;
    }
    __syncthreads();
    const float sb = red[0];

    Y[i * 33 + j] = sig / sb;
    Z[i * 33 + j] = (i == j) ? 1.f : 0.f;
    __syncthreads();

    for (int it = 0; it < 7; it++) {
        float t = (i == j) ? 3.f : 0.f;
        #pragma unroll
        for (int k = 0; k < 32; k++) t -= Z[i * 33 + k] * Y[k * 33 + j];
        T[i * 33 + j] = t;
        __syncthreads();
        float yn = 0.f, zn = 0.f;
        #pragma unroll
        for (int k = 0; k < 32; k++) {
            yn += Y[i * 33 + k] * T[k * 33 + j];
            zn += T[i * 33 + k] * Z[k * 33 + j];
        }
        __syncthreads();
        Y[i * 33 + j] = 0.5f * yn;
        Z[i * 33 + j] = 0.5f * zn;
        __syncthreads();
    }

    const float wmv = Z[i * 33 + j] * rsqrtf(sb) * w[g * GS + i];
    g_wm2[g][i][j] = f2pk(wmv, wmv);

    float bv = wmv * (m_j * (1.0f / NTOT));
    #pragma unroll
    for (int o = 16; o; o >>= 1) bv += __shfl_xor_sync(0xFFFFFFFFu, bv, o);
    if (j == 0) {
        float be = bias[g * GS + i] - bv;
        g_beta2[g][i] = f2pk(be, be);
    }
}

// ---------------------------------------------------------------------------
// Kernel 3: apply. hw-pair f32x2 packing: acc = (y[hw], y[hw+1]).
// x loads natural u64; wm operands from precomputed (w,w) dup table.
// ---------------------------------------------------------------------------
__global__ void __launch_bounds__(256) k_apply(const float* __restrict__ x,
                                               float* __restrict__ out) {
    __shared__ __align__(16) u64 swm[GS * GS];
    __shared__ u64 sbt[GS];

    const int gb = blockIdx.x >> 8;
    for (int t = threadIdx.x; t < GS * GS; t += 256)
        swm[t] = ((const u64*)g_wm2)[gb * GS * GS + t];
    if (threadIdx.x < GS) sbt[threadIdx.x] = g_beta2[gb][threadIdx.x];
    __syncthreads();

    const int p  = ((blockIdx.x & 255) << 8) + threadIdx.x;
    const int hw = (p & 2047) * 2;
    const int b  = p >> 11;
    const size_t base = (size_t)(b * C + gb * GS) * HW + hw;
    const float* xp = x + base;
    float* op = out + base;

    u64 xv[GS];
    #pragma unroll
    for (int e = 0; e < GS; e++) xv[e] = *(const u64*)&xp[(size_t)e * HW];

    #pragma unroll 4
    for (int i = 0; i < GS; i++) {
        u64 a0 = sbt[i], a1 = 0ull;
        const ulonglong2* wr = (const ulonglong2*)&swm[i * GS];
        #pragma unroll
        for (int e2 = 0; e2 < 16; e2++) {
            ulonglong2 wv = wr[e2];
            a0 = ffma2(xv[2 * e2],     wv.x, a0);
            a1 = ffma2(xv[2 * e2 + 1], wv.y, a1);
        }
        *(u64*)&op[(size_t)i * HW] = fadd2(a0, a1);
    }
}

// ---------------------------------------------------------------------------
extern "C" void kernel_launch(void* const* d_in, const int* in_sizes, int n_in,
                              void* d_out, int out_size) {
    const float* x    = (const float*)d_in[0];
    const float* w    = (const float*)d_in[1];
    const float* bias = (const float*)d_in[2];
    float* out        = (float*)d_out;

    k_cov<<<G * NB, 256>>>(x);
    k_ns<<<G, 1024>>>(w, bias);
    k_apply<<<(G * NB * HW / 2) / 256, 256>>>(x, out);
}

// round 7
// speedup vs baseline: 2.0024x; 1.0456x over previous
#include <cuda_runtime.h>
#include <cstdint>

using u64 = unsigned long long;

// Problem constants
constexpr int NB   = 32;
constexpr int C    = 256;
constexpr int HW   = 4096;
constexpr int G    = 8;
constexpr int GS   = 32;
constexpr int NTOT = NB * HW;          // 131072
constexpr float EPSV = 1e-5f;

constexpr int PPG = 64;                // partials per group (b x hw-half)

// Scratch (device globals — no allocations allowed)
__device__ float g_p2[G * PPG][GS][GS];   // per-block cov partials
__device__ float g_p1[G * PPG][GS];       // per-block sum partials
__device__ float g_whi[G][GS][GS];        // whitening matrix, tf32-hi part
__device__ float g_wlo[G][GS][GS];        // tf32-lo residual
__device__ float g_beta[G][GS];           // bias - wm @ mean

// ---- misc PTX ---------------------------------------------------------------
__device__ __forceinline__ uint32_t smem_u32(const void* p) {
    uint32_t a;
    asm("{ .reg .u64 t; cvta.to.shared.u64 t, %1; cvt.u32.u64 %0, t; }"
        : "=r"(a) : "l"(p));
    return a;
}
__device__ __forceinline__ void cp16(uint32_t dst, const void* src) {
    asm volatile("cp.async.cg.shared.global [%0], [%1], 16;"
                 :: "r"(dst), "l"(src) : "memory");
}
__device__ __forceinline__ uint32_t cvt_tf32(float f) {
    uint32_t r; asm("cvt.rna.tf32.f32 %0, %1;" : "=r"(r) : "f"(f)); return r;
}
__device__ __forceinline__ void mma_tf32(float& c0, float& c1, float& c2, float& c3,
                                         uint32_t a0, uint32_t a1, uint32_t a2,
                                         uint32_t a3, uint32_t b0, uint32_t b1) {
    asm volatile(
        "mma.sync.aligned.m16n8k8.row.col.f32.tf32.tf32.f32 "
        "{%0,%1,%2,%3}, {%4,%5,%6,%7}, {%8,%9}, {%0,%1,%2,%3};"
        : "+f"(c0), "+f"(c1), "+f"(c2), "+f"(c3)
        : "r"(a0), "r"(a1), "r"(a2), "r"(a3), "r"(b0), "r"(b1));
}

constexpr int RSTRIDE = 132;           // smem row stride in floats (132%32==4)
constexpr int TILEK   = 128;           // k per tile
constexpr uint32_t ONE_TF = 0x3F800000u;

// ---------------------------------------------------------------------------
// Kernel 1: covariance via mma.sync tf32. 512 blocks = (g, b, hw-half).
// Block computes partial Sigma_g over K=2048. smem tile [32ch][128k] stride
// 132; A fragments double as B fragments (Sigma = X X^T). Two extra ones-MMAs
// accumulate per-channel sums.
// ---------------------------------------------------------------------------
__global__ void __launch_bounds__(256) k_cov(const float* __restrict__ x) {
    __shared__ __align__(16) float sbuf[2][32 * RSTRIDE];   // reused for reduce
    __shared__ float ssum[8][32];

    const int tid = threadIdx.x;
    const int wid = tid >> 5, lane = tid & 31;
    const int g1 = lane >> 2, t4 = lane & 3;   // mma fragment coords

    const int bx = blockIdx.x;
    const int g = bx >> 6, b = (bx >> 1) & 31, s = bx & 1;
    const float* xb = x + (size_t)(b * C + g * GS) * HW + s * 2048;

    const uint32_t sb0 = smem_u32(&sbuf[0][0]);
    const uint32_t sb1 = smem_u32(&sbuf[1][0]);

    auto fill = [&](int t, uint32_t dstb) {
        const float* xt = xb + t * TILEK;
        #pragma unroll
        for (int j = 0; j < 4; j++) {
            int c = j * 256 + tid;
            int row = c >> 5, kq = c & 31;
            cp16(dstb + row * (RSTRIDE * 4) + kq * 16,
                 xt + (size_t)row * HW + kq * 4);
        }
        asm volatile("cp.async.commit_group;" ::: "memory");
    };

    float acc[2][4][4];
    float oacc[2][4];
    #pragma unroll
    for (int m = 0; m < 2; m++) {
        #pragma unroll
        for (int n = 0; n < 4; n++)
            acc[m][n][0] = acc[m][n][1] = acc[m][n][2] = acc[m][n][3] = 0.f;
        oacc[m][0] = oacc[m][1] = oacc[m][2] = oacc[m][3] = 0.f;
    }

    fill(0, sb0);
    for (int t = 0; t < 16; t++) {
        if (t + 1 < 16) {
            fill(t + 1, (t & 1) ? sb0 : sb1);
            asm volatile("cp.async.wait_group 1;" ::: "memory");
        } else {
            asm volatile("cp.async.wait_group 0;" ::: "memory");
        }
        __syncthreads();

        const float* sm = (t & 1) ? &sbuf[1][0] : &sbuf[0][0];
        #pragma unroll
        for (int kk = 0; kk < 2; kk++) {
            const int kb = wid * 16 + kk * 8;
            uint32_t af[2][4];
            #pragma unroll
            for (int m = 0; m < 2; m++) {
                const float* r0 = sm + (m * 16 + g1) * RSTRIDE + kb + t4;
                const float* r1 = sm + (m * 16 + g1 + 8) * RSTRIDE + kb + t4;
                af[m][0] = cvt_tf32(r0[0]);
                af[m][1] = cvt_tf32(r1[0]);
                af[m][2] = cvt_tf32(r0[4]);
                af[m][3] = cvt_tf32(r1[4]);
            }
            #pragma unroll
            for (int m = 0; m < 2; m++) {
                mma_tf32(acc[m][0][0], acc[m][0][1], acc[m][0][2], acc[m][0][3],
                         af[m][0], af[m][1], af[m][2], af[m][3], af[0][0], af[0][2]);
                mma_tf32(acc[m][1][0], acc[m][1][1], acc[m][1][2], acc[m][1][3],
                         af[m][0], af[m][1], af[m][2], af[m][3], af[0][1], af[0][3]);
                mma_tf32(acc[m][2][0], acc[m][2][1], acc[m][2][2], acc[m][2][3],
                         af[m][0], af[m][1], af[m][2], af[m][3], af[1][0], af[1][2]);
                mma_tf32(acc[m][3][0], acc[m][3][1], acc[m][3][2], acc[m][3][3],
                         af[m][0], af[m][1], af[m][2], af[m][3], af[1][1], af[1][3]);
                mma_tf32(oacc[m][0], oacc[m][1], oacc[m][2], oacc[m][3],
                         af[m][0], af[m][1], af[m][2], af[m][3], ONE_TF, ONE_TF);
            }
        }
        __syncthreads();
    }

    // Cross-warp reduction: overlay sred[8][32][33] on sbuf.
    float* sred = &sbuf[0][0];
    #pragma unroll
    for (int m = 0; m < 2; m++) {
        const int r0 = m * 16 + g1, r1 = r0 + 8;
        #pragma unroll
        for (int n = 0; n < 4; n++) {
            const int cb = n * 8 + 2 * t4;
            sred[wid * 1056 + r0 * 33 + cb]     = acc[m][n][0];
            sred[wid * 1056 + r0 * 33 + cb + 1] = acc[m][n][1];
            sred[wid * 1056 + r1 * 33 + cb]     = acc[m][n][2];
            sred[wid * 1056 + r1 * 33 + cb + 1] = acc[m][n][3];
        }
        if (t4 == 0) {
            ssum[wid][r0] = oacc[m][0];
            ssum[wid][r1] = oacc[m][2];
        }
    }
    __syncthreads();

    #pragma unroll
    for (int q = 0; q < 4; q++) {
        const int idx = tid * 4 + q;
        const int r = idx >> 5, c = idx & 31;
        float v = 0.f;
        #pragma unroll
        for (int w = 0; w < 8; w++) v += sred[w * 1056 + r * 33 + c];
        g_p2[bx][r][c] = v;
    }
    if (tid < 32) {
        float v = 0.f;
        #pragma unroll
        for (int w = 0; w < 8; w++) v += ssum[w][tid];
        g_p1[bx][tid] = v;
    }
}

// ---------------------------------------------------------------------------
// Kernel 2: reduce partials -> sigma; sigma^{-1/2} via Newton-Schulz with
// Gershgorin scaling; emit tf32 hi/lo split of the weight-folded whitening
// matrix, plus folded beta.
// ---------------------------------------------------------------------------
__global__ void __launch_bounds__(1024) k_ns(const float* __restrict__ w,
                                             const float* __restrict__ bias) {
    const int g = blockIdx.x;
    const int tid = threadIdx.x;
    const int i = tid >> 5, j = tid & 31;

    __shared__ float Y[32 * 33], Z[32 * 33], T[32 * 33];
    __shared__ float red[32], sS1[32];

    float s2 = 0.f;
    #pragma unroll 4
    for (int p = 0; p < PPG; p++) s2 += g_p2[g * PPG + p][i][j];
    if (tid < 32) {
        float v = 0.f;
        #pragma unroll 4
        for (int p = 0; p < PPG; p++) v += g_p1[g * PPG + p][tid];
        sS1[tid] = v;
    }
    __syncthreads();
    const float m_i = sS1[i], m_j = sS1[j];
    float sig = s2 - m_i * m_j * (1.0f / NTOT) + (i == j ? EPSV : 0.f);

    // Gershgorin bound >= lambda_max
    float av = fabsf(sig);
    #pragma unroll
    for (int o = 16; o; o >>= 1) av += __shfl_xor_sync(0xFFFFFFFFu, av, o);
    if (j == 0) red[i] = av;
    __syncthreads();
    if (tid < 32) {
        float m = red[tid];
        #pragma unroll
        for (int o = 16; o; o >>= 1) m = fmaxf(m, __shfl_xor_sync(0xFFFFFFFFu, m, o));
        if (tid == 0) red[0] = m;
    }
    __syncthreads();
    const float sb = red[0];

    Y[i * 33 + j] = sig / sb;
    Z[i * 33 + j] = (i == j) ? 1.f : 0.f;
    __syncthreads();

    for (int it = 0; it < 7; it++) {
        float t = (i == j) ? 3.f : 0.f;
        #pragma unroll
        for (int k = 0; k < 32; k++) t -= Z[i * 33 + k] * Y[k * 33 + j];
        T[i * 33 + j] = t;
        __syncthreads();
        float yn = 0.f, zn = 0.f;
        #pragma unroll
        for (int k = 0; k < 32; k++) {
            yn += Y[i * 33 + k] * T[k * 33 + j];
            zn += T[i * 33 + k] * Z[k * 33 + j];
        }
        __syncthreads();
        Y[i * 33 + j] = 0.5f * yn;
        Z[i * 33 + j] = 0.5f * zn;
        __syncthreads();
    }

    const float wmv = Z[i * 33 + j] * rsqrtf(sb) * w[g * GS + i];
    const float whi = __uint_as_float(cvt_tf32(wmv));
    g_whi[g][i][j] = whi;
    g_wlo[g][i][j] = __uint_as_float(cvt_tf32(wmv - whi));

    float bv = wmv * (m_j * (1.0f / NTOT));
    #pragma unroll
    for (int o = 16; o; o >>= 1) bv += __shfl_xor_sync(0xFFFFFFFFu, bv, o);
    if (j == 0) g_beta[g][i] = bias[g * GS + i] - bv;
}

// ---------------------------------------------------------------------------
// Kernel 3: apply via mma.sync tf32 with 3xTF32 compensation.
// 256 blocks = (g, b); warp w owns cols [w*512, w*512+512). Per n8 chunk:
// 8 sector-perfect LDG.32, hi/lo split, 24 MMAs (Whi*xhi + Whi*xlo + Wlo*xhi),
// beta folded into the accumulator init, direct STG.64 stores.
// ---------------------------------------------------------------------------
__global__ void __launch_bounds__(256) k_apply(const float* __restrict__ x,
                                               float* __restrict__ out) {
    __shared__ float swh[GS * GS], swl[GS * GS], sbeta[GS];

    const int tid = threadIdx.x;
    const int wid = tid >> 5, lane = tid & 31;
    const int g1 = lane >> 2, t4 = lane & 3;
    const int g = blockIdx.x >> 5, b = blockIdx.x & 31;

    for (int t = tid; t < GS * GS; t += 256) {
        swh[t] = ((const float*)g_whi)[g * GS * GS + t];
        swl[t] = ((const float*)g_wlo)[g * GS * GS + t];
    }
    if (tid < GS) sbeta[tid] = g_beta[g][tid];
    __syncthreads();

    // A fragments: W[m*16 + {g1,g1+8}][kt*8 + {t4,t4+4}], hi and lo parts.
    uint32_t ah[2][4][4], al[2][4][4];
    #pragma unroll
    for (int m = 0; m < 2; m++)
        #pragma unroll
        for (int kt = 0; kt < 4; kt++) {
            const int r0 = (m * 16 + g1) * GS, r1 = r0 + 8 * GS;
            const int c0 = kt * 8 + t4, c1 = c0 + 4;
            ah[m][kt][0] = __float_as_uint(swh[r0 + c0]);
            ah[m][kt][1] = __float_as_uint(swh[r1 + c0]);
            ah[m][kt][2] = __float_as_uint(swh[r0 + c1]);
            ah[m][kt][3] = __float_as_uint(swh[r1 + c1]);
            al[m][kt][0] = __float_as_uint(swl[r0 + c0]);
            al[m][kt][1] = __float_as_uint(swl[r1 + c0]);
            al[m][kt][2] = __float_as_uint(swl[r0 + c1]);
            al[m][kt][3] = __float_as_uint(swl[r1 + c1]);
        }
    const float be0 = sbeta[g1], be8 = sbeta[g1 + 8];
    const float be16 = sbeta[g1 + 16], be24 = sbeta[g1 + 24];

    const size_t base = (size_t)(b * C + g * GS) * HW;
    const float* xb = x + base;
    float* ob = out + base;
    const int col0 = wid * 512;

    for (int it = 0; it < 64; it++) {
        const int n0 = col0 + it * 8;
        const float* xc = xb + n0 + g1;

        uint32_t bh[4][2], bl[4][2];
        #pragma unroll
        for (int kt = 0; kt < 4; kt++) {
            float v0 = xc[(size_t)(kt * 8 + t4) * HW];
            float v1 = xc[(size_t)(kt * 8 + t4 + 4) * HW];
            uint32_t h0 = cvt_tf32(v0), h1 = cvt_tf32(v1);
            bh[kt][0] = h0; bl[kt][0] = cvt_tf32(v0 - __uint_as_float(h0));
            bh[kt][1] = h1; bl[kt][1] = cvt_tf32(v1 - __uint_as_float(h1));
        }

        #pragma unroll
        for (int m = 0; m < 2; m++) {
            float c0 = (m == 0) ? be0 : be16;
            float c2 = (m == 0) ? be8 : be24;
            float c1 = c0, c3 = c2;
            #pragma unroll
            for (int kt = 0; kt < 4; kt++) {
                mma_tf32(c0, c1, c2, c3,
                         ah[m][kt][0], ah[m][kt][1], ah[m][kt][2], ah[m][kt][3],
                         bh[kt][0], bh[kt][1]);
                mma_tf32(c0, c1, c2, c3,
                         ah[m][kt][0], ah[m][kt][1], ah[m][kt][2], ah[m][kt][3],
                         bl[kt][0], bl[kt][1]);
                mma_tf32(c0, c1, c2, c3,
                         al[m][kt][0], al[m][kt][1], al[m][kt][2], al[m][kt][3],
                         bh[kt][0], bh[kt][1]);
            }
            float* o0 = ob + (size_t)(m * 16 + g1) * HW + n0 + 2 * t4;
            float* o1 = o0 + (size_t)8 * HW;
            *(float2*)o0 = make_float2(c0, c1);
            *(float2*)o1 = make_float2(c2, c3);
        }
    }
}

// ---------------------------------------------------------------------------
extern "C" void kernel_launch(void* const* d_in, const int* in_sizes, int n_in,
                              void* d_out, int out_size) {
    const float* x    = (const float*)d_in[0];
    const float* w    = (const float*)d_in[1];
    const float* bias = (const float*)d_in[2];
    float* out        = (float*)d_out;

    k_cov<<<G * NB * 2, 256>>>(x);
    k_ns<<<G, 1024>>>(w, bias);
    k_apply<<<G * NB, 256>>>(x, out);
}

// round 8
// speedup vs baseline: 2.1793x; 1.0883x over previous
#include <cuda_runtime.h>
#include <cstdint>

using u64 = unsigned long long;

// Problem constants
constexpr int NB   = 32;
constexpr int C    = 256;
constexpr int HW   = 4096;
constexpr int G    = 8;
constexpr int GS   = 32;
constexpr int NTOT = NB * HW;          // 131072
constexpr float EPSV = 1e-5f;

constexpr int PPG = 64;                // partials per group (b x hw-half)

// Scratch (device globals — no allocations allowed)
__device__ float g_p2[G * PPG][GS][GS];   // per-block cov partials
__device__ float g_p1[G * PPG][GS];       // per-block sum partials
__device__ float g_whi[G][GS][GS];        // whitening matrix, tf32-hi part
__device__ float g_wlo[G][GS][GS];        // tf32-lo residual
__device__ float g_beta[G][GS];           // bias - wm @ mean

// ---- misc PTX ---------------------------------------------------------------
__device__ __forceinline__ uint32_t smem_u32(const void* p) {
    uint32_t a;
    asm("{ .reg .u64 t; cvta.to.shared.u64 t, %1; cvt.u32.u64 %0, t; }"
        : "=r"(a) : "l"(p));
    return a;
}
__device__ __forceinline__ void cp16(uint32_t dst, const void* src) {
    asm volatile("cp.async.cg.shared.global [%0], [%1], 16;"
                 :: "r"(dst), "l"(src) : "memory");
}
__device__ __forceinline__ uint32_t cvt_tf32(float f) {
    uint32_t r; asm("cvt.rna.tf32.f32 %0, %1;" : "=r"(r) : "f"(f)); return r;
}
__device__ __forceinline__ void mma_tf32(float& c0, float& c1, float& c2, float& c3,
                                         uint32_t a0, uint32_t a1, uint32_t a2,
                                         uint32_t a3, uint32_t b0, uint32_t b1) {
    asm volatile(
        "mma.sync.aligned.m16n8k8.row.col.f32.tf32.tf32.f32 "
        "{%0,%1,%2,%3}, {%4,%5,%6,%7}, {%8,%9}, {%0,%1,%2,%3};"
        : "+f"(c0), "+f"(c1), "+f"(c2), "+f"(c3)
        : "r"(a0), "r"(a1), "r"(a2), "r"(a3), "r"(b0), "r"(b1));
}

constexpr int RSTRIDE = 132;           // smem row stride in floats
constexpr int TILEK   = 128;           // k per tile
constexpr uint32_t ONE_TF = 0x3F800000u;

// ---------------------------------------------------------------------------
// Kernel 1: covariance via mma.sync tf32 (unchanged from R7, known 33 us).
// 512 blocks = (g, b, hw-half); Sigma = X X^T with shared A/B fragments,
// ones-MMAs produce channel sums.
// ---------------------------------------------------------------------------
__global__ void __launch_bounds__(256) k_cov(const float* __restrict__ x) {
    __shared__ __align__(16) float sbuf[2][32 * RSTRIDE];
    __shared__ float ssum[8][32];

    const int tid = threadIdx.x;
    const int wid = tid >> 5, lane = tid & 31;
    const int g1 = lane >> 2, t4 = lane & 3;

    const int bx = blockIdx.x;
    const int g = bx >> 6, b = (bx >> 1) & 31, s = bx & 1;
    const float* xb = x + (size_t)(b * C + g * GS) * HW + s * 2048;

    const uint32_t sb0 = smem_u32(&sbuf[0][0]);
    const uint32_t sb1 = smem_u32(&sbuf[1][0]);

    auto fill = [&](int t, uint32_t dstb) {
        const float* xt = xb + t * TILEK;
        #pragma unroll
        for (int j = 0; j < 4; j++) {
            int c = j * 256 + tid;
            int row = c >> 5, kq = c & 31;
            cp16(dstb + row * (RSTRIDE * 4) + kq * 16,
                 xt + (size_t)row * HW + kq * 4);
        }
        asm volatile("cp.async.commit_group;" ::: "memory");
    };

    float acc[2][4][4];
    float oacc[2][4];
    #pragma unroll
    for (int m = 0; m < 2; m++) {
        #pragma unroll
        for (int n = 0; n < 4; n++)
            acc[m][n][0] = acc[m][n][1] = acc[m][n][2] = acc[m][n][3] = 0.f;
        oacc[m][0] = oacc[m][1] = oacc[m][2] = oacc[m][3] = 0.f;
    }

    fill(0, sb0);
    for (int t = 0; t < 16; t++) {
        if (t + 1 < 16) {
            fill(t + 1, (t & 1) ? sb0 : sb1);
            asm volatile("cp.async.wait_group 1;" ::: "memory");
        } else {
            asm volatile("cp.async.wait_group 0;" ::: "memory");
        }
        __syncthreads();

        const float* sm = (t & 1) ? &sbuf[1][0] : &sbuf[0][0];
        #pragma unroll
        for (int kk = 0; kk < 2; kk++) {
            const int kb = wid * 16 + kk * 8;
            uint32_t af[2][4];
            #pragma unroll
            for (int m = 0; m < 2; m++) {
                const float* r0 = sm + (m * 16 + g1) * RSTRIDE + kb + t4;
                const float* r1 = sm + (m * 16 + g1 + 8) * RSTRIDE + kb + t4;
                af[m][0] = cvt_tf32(r0[0]);
                af[m][1] = cvt_tf32(r1[0]);
                af[m][2] = cvt_tf32(r0[4]);
                af[m][3] = cvt_tf32(r1[4]);
            }
            #pragma unroll
            for (int m = 0; m < 2; m++) {
                mma_tf32(acc[m][0][0], acc[m][0][1], acc[m][0][2], acc[m][0][3],
                         af[m][0], af[m][1], af[m][2], af[m][3], af[0][0], af[0][2]);
                mma_tf32(acc[m][1][0], acc[m][1][1], acc[m][1][2], acc[m][1][3],
                         af[m][0], af[m][1], af[m][2], af[m][3], af[0][1], af[0][3]);
                mma_tf32(acc[m][2][0], acc[m][2][1], acc[m][2][2], acc[m][2][3],
                         af[m][0], af[m][1], af[m][2], af[m][3], af[1][0], af[1][2]);
                mma_tf32(acc[m][3][0], acc[m][3][1], acc[m][3][2], acc[m][3][3],
                         af[m][0], af[m][1], af[m][2], af[m][3], af[1][1], af[1][3]);
                mma_tf32(oacc[m][0], oacc[m][1], oacc[m][2], oacc[m][3],
                         af[m][0], af[m][1], af[m][2], af[m][3], ONE_TF, ONE_TF);
            }
        }
        __syncthreads();
    }

    float* sred = &sbuf[0][0];
    #pragma unroll
    for (int m = 0; m < 2; m++) {
        const int r0 = m * 16 + g1, r1 = r0 + 8;
        #pragma unroll
        for (int n = 0; n < 4; n++) {
            const int cb = n * 8 + 2 * t4;
            sred[wid * 1056 + r0 * 33 + cb]     = acc[m][n][0];
            sred[wid * 1056 + r0 * 33 + cb + 1] = acc[m][n][1];
            sred[wid * 1056 + r1 * 33 + cb]     = acc[m][n][2];
            sred[wid * 1056 + r1 * 33 + cb + 1] = acc[m][n][3];
        }
        if (t4 == 0) {
            ssum[wid][r0] = oacc[m][0];
            ssum[wid][r1] = oacc[m][2];
        }
    }
    __syncthreads();

    #pragma unroll
    for (int q = 0; q < 4; q++) {
        const int idx = tid * 4 + q;
        const int r = idx >> 5, c = idx & 31;
        float v = 0.f;
        #pragma unroll
        for (int w = 0; w < 8; w++) v += sred[w * 1056 + r * 33 + c];
        g_p2[bx][r][c] = v;
    }
    if (tid < 32) {
        float v = 0.f;
        #pragma unroll
        for (int w = 0; w < 8; w++) v += ssum[w][tid];
        g_p1[bx][tid] = v;
    }
}

// ---------------------------------------------------------------------------
// Kernel 2: reduce partials -> sigma; sigma^{-1/2} via 6-iter Newton-Schulz
// (Gershgorin scaling, quadratic convergence: rho(I-A)<=0.19 -> ~1e-13).
// Reduction unrolled 16-deep for MLP. Emits tf32 hi/lo W split + beta.
// ---------------------------------------------------------------------------
__global__ void __launch_bounds__(1024) k_ns(const float* __restrict__ w,
                                             const float* __restrict__ bias) {
    const int g = blockIdx.x;
    const int tid = threadIdx.x;
    const int i = tid >> 5, j = tid & 31;

    __shared__ float Y[32 * 33], Z[32 * 33], T[32 * 33];
    __shared__ float red[32], sS1[32];

    float s2 = 0.f;
    #pragma unroll 16
    for (int p = 0; p < PPG; p++) s2 += g_p2[g * PPG + p][i][j];
    if (tid < 32) {
        float v = 0.f;
        #pragma unroll 16
        for (int p = 0; p < PPG; p++) v += g_p1[g * PPG + p][tid];
        sS1[tid] = v;
    }
    __syncthreads();
    const float m_i = sS1[i], m_j = sS1[j];
    float sig = s2 - m_i * m_j * (1.0f / NTOT) + (i == j ? EPSV : 0.f);

    float av = fabsf(sig);
    #pragma unroll
    for (int o = 16; o; o >>= 1) av += __shfl_xor_sync(0xFFFFFFFFu, av, o);
    if (j == 0) red[i] = av;
    __syncthreads();
    if (tid < 32) {
        float m = red[tid];
        #pragma unroll
        for (int o = 16; o; o >>= 1) m = fmaxf(m, __shfl_xor_sync(0xFFFFFFFFu, m, o));
        if (tid == 0) red[0] = m;
    }
    __syncthreads();
    const float sb = red[0];

    Y[i * 33 + j] = sig / sb;
    Z[i * 33 + j] = (i == j) ? 1.f : 0.f;
    __syncthreads();

    for (int it = 0; it < 6; it++) {
        float t = (i == j) ? 3.f : 0.f;
        #pragma unroll
        for (int k = 0; k < 32; k++) t -= Z[i * 33 + k] * Y[k * 33 + j];
        T[i * 33 + j] = t;
        __syncthreads();
        float yn = 0.f, zn = 0.f;
        #pragma unroll
        for (int k = 0; k < 32; k++) {
            yn += Y[i * 33 + k] * T[k * 33 + j];
            zn += T[i * 33 + k] * Z[k * 33 + j];
        }
        __syncthreads();
        Y[i * 33 + j] = 0.5f * yn;
        Z[i * 33 + j] = 0.5f * zn;
        __syncthreads();
    }

    const float wmv = Z[i * 33 + j] * rsqrtf(sb) * w[g * GS + i];
    const float whi = __uint_as_float(cvt_tf32(wmv));
    g_whi[g][i][j] = whi;
    g_wlo[g][i][j] = __uint_as_float(cvt_tf32(wmv - whi));

    float bv = wmv * (m_j * (1.0f / NTOT));
    #pragma unroll
    for (int o = 16; o; o >>= 1) bv += __shfl_xor_sync(0xFFFFFFFFu, bv, o);
    if (j == 0) g_beta[g][i] = bias[g * GS + i] - bv;
}

// ---------------------------------------------------------------------------
// Kernel 3: apply via mma.sync tf32, 2-term compensation:
//   y = (Whi + Wlo) * tf32(x) + beta      (dropped W*xlo ~ 1.2e-4 rel)
// 512 blocks x 128 threads = (g, b, col-half); warp w owns 512 cols.
// Per n8 chunk: 8 sector-perfect LDG.32, 8 cvt, 16 MMA, STG.64 stores.
// ---------------------------------------------------------------------------
__global__ void __launch_bounds__(128) k_apply(const float* __restrict__ x,
                                               float* __restrict__ out) {
    __shared__ float swh[GS * GS], swl[GS * GS], sbeta[GS];

    const int tid = threadIdx.x;
    const int wid = tid >> 5, lane = tid & 31;
    const int g1 = lane >> 2, t4 = lane & 3;
    const int bx = blockIdx.x;
    const int g = bx >> 6, b = (bx >> 1) & 31, s = bx & 1;

    for (int t = tid; t < GS * GS; t += 128) {
        swh[t] = ((const float*)g_whi)[g * GS * GS + t];
        swl[t] = ((const float*)g_wlo)[g * GS * GS + t];
    }
    if (tid < GS) sbeta[tid] = g_beta[g][tid];
    __syncthreads();

    uint32_t ah[2][4][4], al[2][4][4];
    #pragma unroll
    for (int m = 0; m < 2; m++)
        #pragma unroll
        for (int kt = 0; kt < 4; kt++) {
            const int r0 = (m * 16 + g1) * GS, r1 = r0 + 8 * GS;
            const int c0 = kt * 8 + t4, c1 = c0 + 4;
            ah[m][kt][0] = __float_as_uint(swh[r0 + c0]);
            ah[m][kt][1] = __float_as_uint(swh[r1 + c0]);
            ah[m][kt][2] = __float_as_uint(swh[r0 + c1]);
            ah[m][kt][3] = __float_as_uint(swh[r1 + c1]);
            al[m][kt][0] = __float_as_uint(swl[r0 + c0]);
            al[m][kt][1] = __float_as_uint(swl[r1 + c0]);
            al[m][kt][2] = __float_as_uint(swl[r0 + c1]);
            al[m][kt][3] = __float_as_uint(swl[r1 + c1]);
        }
    const float be0 = sbeta[g1], be8 = sbeta[g1 + 8];
    const float be16 = sbeta[g1 + 16], be24 = sbeta[g1 + 24];

    const size_t base = (size_t)(b * C + g * GS) * HW;
    const float* xb = x + base;
    float* ob = out + base;
    const int col0 = s * 2048 + wid * 512;

    #pragma unroll 2
    for (int it = 0; it < 64; it++) {
        const int n0 = col0 + it * 8;
        const float* xc = xb + n0 + g1;

        uint32_t bh[4][2];
        #pragma unroll
        for (int kt = 0; kt < 4; kt++) {
            bh[kt][0] = cvt_tf32(xc[(size_t)(kt * 8 + t4) * HW]);
            bh[kt][1] = cvt_tf32(xc[(size_t)(kt * 8 + t4 + 4) * HW]);
        }

        #pragma unroll
        for (int m = 0; m < 2; m++) {
            float c0 = (m == 0) ? be0 : be16;
            float c2 = (m == 0) ? be8 : be24;
            float c1 = c0, c3 = c2;
            #pragma unroll
            for (int kt = 0; kt < 4; kt++) {
                mma_tf32(c0, c1, c2, c3,
                         ah[m][kt][0], ah[m][kt][1], ah[m][kt][2], ah[m][kt][3],
                         bh[kt][0], bh[kt][1]);
                mma_tf32(c0, c1, c2, c3,
                         al[m][kt][0], al[m][kt][1], al[m][kt][2], al[m][kt][3],
                         bh[kt][0], bh[kt][1]);
            }
            float* o0 = ob + (size_t)(m * 16 + g1) * HW + n0 + 2 * t4;
            float* o1 = o0 + (size_t)8 * HW;
            *(float2*)o0 = make_float2(c0, c1);
            *(float2*)o1 = make_float2(c2, c3);
        }
    }
}

// ---------------------------------------------------------------------------
extern "C" void kernel_launch(void* const* d_in, const int* in_sizes, int n_in,
                              void* d_out, int out_size) {
    const float* x    = (const float*)d_in[0];
    const float* w    = (const float*)d_in[1];
    const float* bias = (const float*)d_in[2];
    float* out        = (float*)d_out;

    k_cov<<<G * NB * 2, 256>>>(x);
    k_ns<<<G, 1024>>>(w, bias);
    k_apply<<<G * NB * 2, 128>>>(x, out);
}